// round 4
// baseline (speedup 1.0000x reference)
#include <cuda_runtime.h>

#define BB   4
#define NN   8000
#define CC   64
#define KK   32
#define DD   9
#define NCLS 13
#define BN   (BB*NN)

#define SL   4            // candidate slices
#define SLN  (NN/SL)      // 2000 candidates per slice
#define CAP  256          // per-thread append buffer
#define NS   250          // prepass samples per slice
#define TSEL 20           // take 20th-smallest sample as threshold
#define ENC_PTS 64

__device__ float  g_G1[BN*CC];
__device__ float  g_G2[BN*CC];
__device__ float4 g_pts[BN];
__device__ int    g_idx[BN*KK];
__device__ unsigned long long g_part[SL*BN*KK];   // slice partial results
__device__ int    g_pcnt[SL*BN];

__device__ __forceinline__ float inf_f() { return __int_as_float(0x7f800000); }

// ---------------------------------------------------------------------------
// Encoder (R2 version — best measured): feats = relu(x@w1+b1)@w2+b2;
// G1 = feats@f1w; G2 = feats@f2w. 64 pts/block, 4 workers/point.
// ---------------------------------------------------------------------------
__global__ __launch_bounds__(256) void encoder_kernel(
    const float* __restrict__ x,
    const float* __restrict__ w1, const float* __restrict__ b1v,
    const float* __restrict__ w2, const float* __restrict__ b2v,
    const float* __restrict__ f1w, const float* __restrict__ f2w)
{
    __shared__ float sx[ENC_PTS][12];
    __shared__ float sh[ENC_PTS][68];
    __shared__ float sf[ENC_PTS][68];

    int tid = threadIdx.x;
    int p = tid >> 2, t = tid & 3;
    int g0 = blockIdx.x * ENC_PTS;

    for (int i = tid; i < ENC_PTS*DD; i += 256) {
        int pp = i / DD, d = i % DD;
        sx[pp][d] = x[(g0 + pp)*DD + d];
    }
    __syncthreads();

    int g = g0 + p;
    if (t == 0) {
        float a = sx[p][0], b = sx[p][1], c = sx[p][2];
        g_pts[g] = make_float4(a, b, c, a*a + b*b + c*c);
    }

    float acc[16];

    // layer 1: hidden = relu(x @ w1 + b1)
    {
        const float4* bq = (const float4*)b1v + t*4;
        #pragma unroll
        for (int c4 = 0; c4 < 4; c4++) {
            float4 bv = bq[c4];
            acc[c4*4+0]=bv.x; acc[c4*4+1]=bv.y; acc[c4*4+2]=bv.z; acc[c4*4+3]=bv.w;
        }
        #pragma unroll
        for (int d = 0; d < DD; d++) {
            float xv = sx[p][d];
            const float4* wv = (const float4*)(w1 + d*CC + t*16);
            #pragma unroll
            for (int c4 = 0; c4 < 4; c4++) {
                float4 w = wv[c4];
                acc[c4*4+0] = fmaf(xv, w.x, acc[c4*4+0]);
                acc[c4*4+1] = fmaf(xv, w.y, acc[c4*4+1]);
                acc[c4*4+2] = fmaf(xv, w.z, acc[c4*4+2]);
                acc[c4*4+3] = fmaf(xv, w.w, acc[c4*4+3]);
            }
        }
        #pragma unroll
        for (int c = 0; c < 16; c++) sh[p][t*16 + c] = fmaxf(acc[c], 0.f);
    }
    __syncthreads();

    // layer 2: feats = hidden @ w2 + b2
    {
        const float4* bq = (const float4*)b2v + t*4;
        #pragma unroll
        for (int c4 = 0; c4 < 4; c4++) {
            float4 bv = bq[c4];
            acc[c4*4+0]=bv.x; acc[c4*4+1]=bv.y; acc[c4*4+2]=bv.z; acc[c4*4+3]=bv.w;
        }
        #pragma unroll 4
        for (int j = 0; j < CC; j++) {
            float hv = sh[p][j];
            const float4* wv = (const float4*)(w2 + j*CC + t*16);
            #pragma unroll
            for (int c4 = 0; c4 < 4; c4++) {
                float4 w = wv[c4];
                acc[c4*4+0] = fmaf(hv, w.x, acc[c4*4+0]);
                acc[c4*4+1] = fmaf(hv, w.y, acc[c4*4+1]);
                acc[c4*4+2] = fmaf(hv, w.z, acc[c4*4+2]);
                acc[c4*4+3] = fmaf(hv, w.w, acc[c4*4+3]);
            }
        }
        #pragma unroll
        for (int c = 0; c < 16; c++) sf[p][t*16 + c] = acc[c];
    }
    __syncthreads();

    // G1 = feats @ f1w
    {
        #pragma unroll
        for (int c = 0; c < 16; c++) acc[c] = 0.f;
        #pragma unroll 4
        for (int j = 0; j < CC; j++) {
            float fv = sf[p][j];
            const float4* wv = (const float4*)(f1w + j*CC + t*16);
            #pragma unroll
            for (int c4 = 0; c4 < 4; c4++) {
                float4 w = wv[c4];
                acc[c4*4+0] = fmaf(fv, w.x, acc[c4*4+0]);
                acc[c4*4+1] = fmaf(fv, w.y, acc[c4*4+1]);
                acc[c4*4+2] = fmaf(fv, w.z, acc[c4*4+2]);
                acc[c4*4+3] = fmaf(fv, w.w, acc[c4*4+3]);
            }
        }
        float4* o = (float4*)(g_G1 + g*CC + t*16);
        #pragma unroll
        for (int c4 = 0; c4 < 4; c4++)
            o[c4] = make_float4(acc[c4*4+0], acc[c4*4+1], acc[c4*4+2], acc[c4*4+3]);
    }

    // G2 = feats @ f2w
    {
        #pragma unroll
        for (int c = 0; c < 16; c++) acc[c] = 0.f;
        #pragma unroll 4
        for (int j = 0; j < CC; j++) {
            float fv = sf[p][j];
            const float4* wv = (const float4*)(f2w + j*CC + t*16);
            #pragma unroll
            for (int c4 = 0; c4 < 4; c4++) {
                float4 w = wv[c4];
                acc[c4*4+0] = fmaf(fv, w.x, acc[c4*4+0]);
                acc[c4*4+1] = fmaf(fv, w.y, acc[c4*4+1]);
                acc[c4*4+2] = fmaf(fv, w.z, acc[c4*4+2]);
                acc[c4*4+3] = fmaf(fv, w.w, acc[c4*4+3]);
            }
        }
        float4* o = (float4*)(g_G2 + g*CC + t*16);
        #pragma unroll
        for (int c4 = 0; c4 < 4; c4++)
            o[c4] = make_float4(acc[c4*4+0], acc[c4*4+1], acc[c4*4+2], acc[c4*4+3]);
    }
}

// ---------------------------------------------------------------------------
// Exact 32-smallest of buf[0..cnt) via 8x4 group-max insert. Writes survivors
// to buf[0..32); returns worst (32nd smallest).
// ---------------------------------------------------------------------------
__device__ __noinline__ float compact32(unsigned long long* buf, int cnt,
                                        float* kd, int* ki)
{
    const float INF = inf_f();
    float gm[8];
    #pragma unroll
    for (int i = 0; i < 8; i++) gm[i] = INF;
    #pragma unroll 1
    for (int i = 0; i < KK; i++) { kd[i] = INF; ki[i] = 0; }
    float worst = INF;

    #pragma unroll 1
    for (int tix = 0; tix < cnt; tix++) {
        unsigned long long v = buf[tix];
        float s = __uint_as_float((unsigned)(v >> 32));
        if (s < worst) {
            int id = (int)(unsigned)v;
            int gsel = 0; float gv = gm[0];
            #pragma unroll
            for (int i = 1; i < 8; i++) if (gm[i] > gv) { gv = gm[i]; gsel = i; }
            int base = gsel*4;
            float v0 = kd[base], v1 = kd[base+1], v2 = kd[base+2], v3 = kd[base+3];
            int e = 0; float ev = v0;
            if (v1 > ev) { ev = v1; e = 1; }
            if (v2 > ev) { ev = v2; e = 2; }
            if (v3 > ev) { ev = v3; e = 3; }
            kd[base+e] = s; ki[base+e] = id;
            float ngm = fmaxf(fmaxf(e==0?s:v0, e==1?s:v1),
                              fmaxf(e==2?s:v2, e==3?s:v3));
            #pragma unroll
            for (int i = 0; i < 8; i++) if (i == gsel) gm[i] = ngm;
            float w8 = gm[0];
            #pragma unroll
            for (int i = 1; i < 8; i++) w8 = fmaxf(w8, gm[i]);
            worst = w8;
        }
    }
    #pragma unroll 1
    for (int i = 0; i < KK; i++)
        buf[i] = ((unsigned long long)__float_as_uint(kd[i]) << 32) |
                 (unsigned)ki[i];
    return worst;
}

// ---------------------------------------------------------------------------
// KNN scan: grid (32, BB, SL). Block stages its 2000-candidate slice (32KB),
// each thread handles one query vs this slice. s = |pj|^2 - 2 pi.pj (order-
// preserving shift). Threshold = 20th smallest of 250 slice samples (rank(thr)
// >= 32 w.p. 1-2e-9, so every global-top-32 member of the slice survives).
// Appends are single predicated stores — no divergent branches in hot loop.
// Writes exact slice-top-min(cnt,32) to g_part.
// ---------------------------------------------------------------------------
__global__ __launch_bounds__(256) void knn_scan_kernel() {
    __shared__ float4 sp[SLN];
    int b = blockIdx.y, sl = blockIdx.z;
    int jbase = sl * SLN;
    {
        const float4* src = g_pts + b*NN + jbase;
        for (int j = threadIdx.x; j < SLN; j += 256) sp[j] = src[j];
    }
    __syncthreads();

    int q = blockIdx.x * 256 + threadIdx.x;
    if (q >= NN) return;

    float4 me = g_pts[b*NN + q];
    float mx = -2.f*me.x, my = -2.f*me.y, mz = -2.f*me.z;
    const float INF = inf_f();

    // prepass: tw = TSEL-th smallest of NS stride-8 samples
    float t[TSEL];
    #pragma unroll
    for (int i = 0; i < TSEL; i++) t[i] = INF;
    float tw = INF;
    #pragma unroll 1
    for (int k = 0; k < NS; k++) {
        float4 c = sp[k*8];
        float s = fmaf(c.x, mx, c.w);
        s = fmaf(c.y, my, s);
        s = fmaf(c.z, mz, s);
        if (s < tw) {
            int am = 0; float mv = t[0];
            #pragma unroll
            for (int i = 1; i < TSEL; i++) if (t[i] > mv) { mv = t[i]; am = i; }
            #pragma unroll
            for (int i = 0; i < TSEL; i++) if (i == am) t[i] = s;
            mv = t[0];
            #pragma unroll
            for (int i = 1; i < TSEL; i++) mv = fmaxf(mv, t[i]);
            tw = mv;
        }
    }

    // main scan: predicated appends
    unsigned long long buf[CAP];
    float kd[KK]; int ki[KK];
    float thr = tw;
    int cnt = 0;

    #pragma unroll 1
    for (int jg = 0; jg < SLN/8; jg++) {
        int j0 = jg*8;
        float s[8];
        #pragma unroll
        for (int u = 0; u < 8; u++) {
            float4 c = sp[j0 + u];
            float ss = fmaf(c.x, mx, c.w);
            ss = fmaf(c.y, my, ss);
            s[u] = fmaf(c.z, mz, ss);
        }
        #pragma unroll
        for (int u = 0; u < 8; u++) {
            bool a = s[u] < thr;
            unsigned long long pk =
                ((unsigned long long)__float_as_uint(s[u]) << 32)
                | (unsigned)(jbase + j0 + u);
            if (a) buf[cnt] = pk;          // single predicated STL.64
            cnt += a ? 1 : 0;
        }
        if (cnt >= CAP - 8) {              // rare overflow: exact compaction
            float w2 = compact32(buf, cnt, kd, ki);
            thr = fminf(thr, w2);
            cnt = KK;
        }
    }

    if (cnt > KK) {
        compact32(buf, cnt, kd, ki);
        cnt = KK;
    }

    int gq = (sl*BB + b)*NN + q;
    g_pcnt[gq] = cnt;
    unsigned long long* o = g_part + gq*KK;
    #pragma unroll 1
    for (int i = 0; i < cnt; i++) o[i] = buf[i];
}

// ---------------------------------------------------------------------------
// Merge: per query, exact 32-smallest over the union of slice survivors
// (union is a superset of the true top-32 -> exact).
// ---------------------------------------------------------------------------
__global__ __launch_bounds__(256) void knn_merge_kernel() {
    int g = blockIdx.x * 256 + threadIdx.x;   // grid = BN/256 exactly
    int b = g / NN, q = g % NN;

    const float INF = inf_f();
    float gm[8];
    float kd[KK]; int ki[KK];
    #pragma unroll
    for (int i = 0; i < 8; i++) gm[i] = INF;
    #pragma unroll 1
    for (int i = 0; i < KK; i++) { kd[i] = INF; ki[i] = q; }
    float worst = INF;

    #pragma unroll 1
    for (int sl = 0; sl < SL; sl++) {
        int gq = (sl*BB + b)*NN + q;
        int cnt = g_pcnt[gq];
        const unsigned long long* src = g_part + gq*KK;
        #pragma unroll 1
        for (int i = 0; i < cnt; i++) {
            unsigned long long v = src[i];
            float s = __uint_as_float((unsigned)(v >> 32));
            if (s < worst) {
                int id = (int)(unsigned)v;
                int gsel = 0; float gv = gm[0];
                #pragma unroll
                for (int i2 = 1; i2 < 8; i2++) if (gm[i2] > gv) { gv = gm[i2]; gsel = i2; }
                int base = gsel*4;
                float v0 = kd[base], v1 = kd[base+1], v2 = kd[base+2], v3 = kd[base+3];
                int e = 0; float ev = v0;
                if (v1 > ev) { ev = v1; e = 1; }
                if (v2 > ev) { ev = v2; e = 2; }
                if (v3 > ev) { ev = v3; e = 3; }
                kd[base+e] = s; ki[base+e] = id;
                float ngm = fmaxf(fmaxf(e==0?s:v0, e==1?s:v1),
                                  fmaxf(e==2?s:v2, e==3?s:v3));
                #pragma unroll
                for (int i2 = 0; i2 < 8; i2++) if (i2 == gsel) gm[i2] = ngm;
                float w8 = gm[0];
                #pragma unroll
                for (int i2 = 1; i2 < 8; i2++) w8 = fmaxf(w8, gm[i2]);
                worst = w8;
            }
        }
    }

    int* o = g_idx + g*KK;
    #pragma unroll 1
    for (int i = 0; i < KK; i++) o[i] = ki[i];
}

// ---------------------------------------------------------------------------
// Fuse (both branches) + classifier.
// ---------------------------------------------------------------------------
__global__ __launch_bounds__(256) void fuse_kernel(
    const float* __restrict__ f1b, const float* __restrict__ f2b,
    const float* __restrict__ cw1, const float* __restrict__ cb1,
    const float* __restrict__ cw2, const float* __restrict__ cb2,
    float* __restrict__ out)
{
    __shared__ float sfused[4][CC];
    __shared__ float shid[4][CC/2];
    __shared__ int   sidx[4][KK];

    int tid = threadIdx.x;
    int p = tid >> 6, c = tid & 63;
    int g = blockIdx.x*4 + p;

    if (c < KK) sidx[p][c] = g_idx[g*KK + c];
    __syncthreads();

    int b = g / NN;
    int rowbase = b*NN;

    float g1i = g_G1[g*CC + c];
    float g2i = g_G2[g*CC + c];
    float bb1 = f1b[c] - g1i;
    float bb2 = f2b[c] - g2i;
    float m1 = 0.f, m2 = 0.f;
    #pragma unroll 8
    for (int k = 0; k < KK; k++) {
        int j = sidx[p][k] + rowbase;
        m1 = fmaxf(m1, g_G1[j*CC + c] + bb1);
        m2 = fmaxf(m2, g_G2[j*CC + c] + bb2);
    }
    sfused[p][c] = m1 + m2;
    __syncthreads();

    if (c < CC/2) {
        float a = cb1[c];
        #pragma unroll
        for (int u = 0; u < CC; u++) a = fmaf(sfused[p][u], cw1[u*(CC/2) + c], a);
        shid[p][c] = fmaxf(a, 0.f);
    }
    __syncthreads();

    if (c < NCLS) {
        float a = cb2[c];
        #pragma unroll
        for (int u = 0; u < CC/2; u++) a = fmaf(shid[p][u], cw2[u*NCLS + c], a);
        out[g*NCLS + c] = a;
    }
}

extern "C" void kernel_launch(void* const* d_in, const int* in_sizes, int n_in,
                              void* d_out, int out_size) {
    const float* x      = (const float*)d_in[0];
    const float* enc_w1 = (const float*)d_in[1];
    const float* enc_b1 = (const float*)d_in[2];
    const float* enc_w2 = (const float*)d_in[3];
    const float* enc_b2 = (const float*)d_in[4];
    const float* f1_w   = (const float*)d_in[5];
    const float* f1_b   = (const float*)d_in[6];
    const float* f2_w   = (const float*)d_in[7];
    const float* f2_b   = (const float*)d_in[8];
    const float* cls_w1 = (const float*)d_in[9];
    const float* cls_b1 = (const float*)d_in[10];
    const float* cls_w2 = (const float*)d_in[11];
    const float* cls_b2 = (const float*)d_in[12];

    encoder_kernel<<<BN/ENC_PTS, 256>>>(x, enc_w1, enc_b1, enc_w2, enc_b2,
                                        f1_w, f2_w);

    dim3 sg((NN + 255)/256, BB, SL);
    knn_scan_kernel<<<sg, 256>>>();
    knn_merge_kernel<<<BN/256, 256>>>();

    fuse_kernel<<<BN/4, 256>>>(f1_b, f2_b, cls_w1, cls_b1, cls_w2, cls_b2,
                               (float*)d_out);
}

// round 5
// speedup vs baseline: 1.7250x; 1.7250x over previous
#include <cuda_runtime.h>

#define BB   4
#define NN   8000
#define CC   64
#define KK   32
#define DD   9
#define NCLS 13
#define BN   (BB*NN)

#define CAP  128          // per-thread candidate buffer slots (local mem)

__device__ float  g_G1[BN*CC];
__device__ float  g_G2[BN*CC];
__device__ float4 g_pts[BN];
__device__ int    g_idx[BN*KK];

__device__ __forceinline__ float inf_f() { return __int_as_float(0x7f800000); }

// ---------------------------------------------------------------------------
// Encoder (R1 version — best measured 101us): one thread per point.
// feats = relu(x@w1+b1)@w2+b2 ; G1 = feats@f1w ; G2 = feats@f2w
// ---------------------------------------------------------------------------
__global__ __launch_bounds__(256) void encoder_kernel(
    const float* __restrict__ x,
    const float* __restrict__ w1, const float* __restrict__ b1v,
    const float* __restrict__ w2, const float* __restrict__ b2v,
    const float* __restrict__ f1w, const float* __restrict__ f2w)
{
    int g = blockIdx.x * blockDim.x + threadIdx.x;
    if (g >= BN) return;

    float xr[DD];
    #pragma unroll
    for (int d = 0; d < DD; d++) xr[d] = x[g*DD + d];
    g_pts[g] = make_float4(xr[0], xr[1], xr[2],
                           xr[0]*xr[0] + xr[1]*xr[1] + xr[2]*xr[2]);

    float acc[CC];

    // hidden = relu(x @ w1 + b1)
    {
        const float4* bq = (const float4*)b1v;
        #pragma unroll
        for (int c4 = 0; c4 < CC/4; c4++) {
            float4 bv = bq[c4];
            acc[c4*4+0]=bv.x; acc[c4*4+1]=bv.y; acc[c4*4+2]=bv.z; acc[c4*4+3]=bv.w;
        }
        #pragma unroll
        for (int d = 0; d < DD; d++) {
            float xv = xr[d];
            const float4* wv = (const float4*)(w1 + d*CC);
            #pragma unroll
            for (int c4 = 0; c4 < CC/4; c4++) {
                float4 w = wv[c4];
                acc[c4*4+0] = fmaf(xv, w.x, acc[c4*4+0]);
                acc[c4*4+1] = fmaf(xv, w.y, acc[c4*4+1]);
                acc[c4*4+2] = fmaf(xv, w.z, acc[c4*4+2]);
                acc[c4*4+3] = fmaf(xv, w.w, acc[c4*4+3]);
            }
        }
    }
    float hloc[CC];
    #pragma unroll
    for (int c = 0; c < CC; c++) hloc[c] = fmaxf(acc[c], 0.f);

    // feats = hidden @ w2 + b2
    {
        const float4* bq = (const float4*)b2v;
        #pragma unroll
        for (int c4 = 0; c4 < CC/4; c4++) {
            float4 bv = bq[c4];
            acc[c4*4+0]=bv.x; acc[c4*4+1]=bv.y; acc[c4*4+2]=bv.z; acc[c4*4+3]=bv.w;
        }
        #pragma unroll 1
        for (int j = 0; j < CC; j++) {
            float hv = hloc[j];
            const float4* wv = (const float4*)(w2 + j*CC);
            #pragma unroll
            for (int c4 = 0; c4 < CC/4; c4++) {
                float4 w = wv[c4];
                acc[c4*4+0] = fmaf(hv, w.x, acc[c4*4+0]);
                acc[c4*4+1] = fmaf(hv, w.y, acc[c4*4+1]);
                acc[c4*4+2] = fmaf(hv, w.z, acc[c4*4+2]);
                acc[c4*4+3] = fmaf(hv, w.w, acc[c4*4+3]);
            }
        }
    }
    float floc[CC];
    #pragma unroll
    for (int c = 0; c < CC; c++) floc[c] = acc[c];

    // G1 = feats @ f1w
    #pragma unroll
    for (int c = 0; c < CC; c++) acc[c] = 0.f;
    #pragma unroll 1
    for (int j = 0; j < CC; j++) {
        float fv = floc[j];
        const float4* wv = (const float4*)(f1w + j*CC);
        #pragma unroll
        for (int c4 = 0; c4 < CC/4; c4++) {
            float4 w = wv[c4];
            acc[c4*4+0] = fmaf(fv, w.x, acc[c4*4+0]);
            acc[c4*4+1] = fmaf(fv, w.y, acc[c4*4+1]);
            acc[c4*4+2] = fmaf(fv, w.z, acc[c4*4+2]);
            acc[c4*4+3] = fmaf(fv, w.w, acc[c4*4+3]);
        }
    }
    {
        float4* o = (float4*)g_G1 + g*(CC/4);
        #pragma unroll
        for (int c4 = 0; c4 < CC/4; c4++)
            o[c4] = make_float4(acc[c4*4+0], acc[c4*4+1], acc[c4*4+2], acc[c4*4+3]);
    }

    // G2 = feats @ f2w
    #pragma unroll
    for (int c = 0; c < CC; c++) acc[c] = 0.f;
    #pragma unroll 1
    for (int j = 0; j < CC; j++) {
        float fv = floc[j];
        const float4* wv = (const float4*)(f2w + j*CC);
        #pragma unroll
        for (int c4 = 0; c4 < CC/4; c4++) {
            float4 w = wv[c4];
            acc[c4*4+0] = fmaf(fv, w.x, acc[c4*4+0]);
            acc[c4*4+1] = fmaf(fv, w.y, acc[c4*4+1]);
            acc[c4*4+2] = fmaf(fv, w.z, acc[c4*4+2]);
            acc[c4*4+3] = fmaf(fv, w.w, acc[c4*4+3]);
        }
    }
    {
        float4* o = (float4*)g_G2 + g*(CC/4);
        #pragma unroll
        for (int c4 = 0; c4 < CC/4; c4++)
            o[c4] = make_float4(acc[c4*4+0], acc[c4*4+1], acc[c4*4+2], acc[c4*4+3]);
    }
}

// ---------------------------------------------------------------------------
// Exact 32-smallest of buf[0..cnt) via 8x4 group-max insert (first-seen kept
// among equals). Writes survivors to buf[0..32); returns worst (32nd).
// ---------------------------------------------------------------------------
__device__ __noinline__ float compact32(unsigned long long* buf, int cnt,
                                        float* kd, int* ki)
{
    const float INF = inf_f();
    float gm[8];
    #pragma unroll
    for (int i = 0; i < 8; i++) gm[i] = INF;
    #pragma unroll 1
    for (int i = 0; i < KK; i++) { kd[i] = INF; ki[i] = 0; }
    float worst = INF;

    #pragma unroll 1
    for (int tix = 0; tix < cnt; tix++) {
        unsigned long long v = buf[tix];
        float s = __uint_as_float((unsigned)(v >> 32));
        if (s < worst) {
            int id = (int)(unsigned)v;
            int gsel = 0; float gv = gm[0];
            #pragma unroll
            for (int i = 1; i < 8; i++) if (gm[i] > gv) { gv = gm[i]; gsel = i; }
            int base = gsel*4;
            float v0 = kd[base], v1 = kd[base+1], v2 = kd[base+2], v3 = kd[base+3];
            int e = 0; float ev = v0;
            if (v1 > ev) { ev = v1; e = 1; }
            if (v2 > ev) { ev = v2; e = 2; }
            if (v3 > ev) { ev = v3; e = 3; }
            kd[base+e] = s; ki[base+e] = id;
            float ngm = fmaxf(fmaxf(e==0?s:v0, e==1?s:v1),
                              fmaxf(e==2?s:v2, e==3?s:v3));
            #pragma unroll
            for (int i = 0; i < 8; i++) if (i == gsel) gm[i] = ngm;
            float w8 = gm[0];
            #pragma unroll
            for (int i = 1; i < 8; i++) w8 = fmaxf(w8, gm[i]);
            worst = w8;
        }
    }
    #pragma unroll 1
    for (int i = 0; i < KK; i++)
        buf[i] = ((unsigned long long)__float_as_uint(kd[i]) << 32) |
                 (unsigned)ki[i];
    return worst;
}

// ---------------------------------------------------------------------------
// Exact 32-NN, compaction-driven threshold. All 8000 candidates staged in
// 128KB smem; s = |pj|^2 - 2 pi.pj (order-preserving shift of sq-distance).
// Hot loop is branch-free (predicated append); compactions are rare and
// warp-synchronized via __any_sync (loop is warp-uniform). No prepass, no
// fallback: thr starts at INF so the first compaction is exact.
// ---------------------------------------------------------------------------
__global__ __launch_bounds__(256) void knn_kernel() {
    extern __shared__ float4 sp[];
    int b = blockIdx.y;
    for (int j = threadIdx.x; j < NN; j += 256) sp[j] = g_pts[b*NN + j];
    __syncthreads();

    int q = blockIdx.x * 256 + threadIdx.x;
    if (q >= NN) q = NN - 1;              // clamp (no exit: ballot safety)

    float4 me = sp[q];
    float mx = -2.f*me.x, my = -2.f*me.y, mz = -2.f*me.z;
    const float INF = inf_f();

    unsigned long long buf[CAP];
    float kd[KK]; int ki[KK];
    float thr = INF;
    int cnt = 0;

    #pragma unroll 1
    for (int jg = 0; jg < NN/8; jg++) {
        int j0 = jg*8;
        float s[8];
        #pragma unroll
        for (int u = 0; u < 8; u++) {
            float4 c = sp[j0 + u];
            float ss = fmaf(c.x, mx, c.w);
            ss = fmaf(c.y, my, ss);
            s[u] = fmaf(c.z, mz, ss);
        }
        #pragma unroll
        for (int u = 0; u < 8; u++) {
            bool a = s[u] < thr;
            unsigned long long pk =
                ((unsigned long long)__float_as_uint(s[u]) << 32)
                | (unsigned)(j0 + u);
            if (a) buf[cnt] = pk;          // @P STL.64 — no branch
            cnt += a ? 1 : 0;
        }
        if (__any_sync(0xffffffffu, cnt >= CAP - 8)) {
            // warp-synchronized exact compaction to top-32-so-far
            float w2 = compact32(buf, cnt, kd, ki);
            thr = fminf(thr, w2);
            cnt = KK;
        }
    }

    compact32(buf, cnt, kd, ki);           // cnt >= 32 always
    int* o = g_idx + (b*NN + q)*KK;
    #pragma unroll 1
    for (int i = 0; i < KK; i++) o[i] = ki[i];
}

// ---------------------------------------------------------------------------
// Fuse (both branches) + classifier. msg = relu(G[nbr]-G[i]+b); max over K;
// fused = m1+m2; then 64->32->13 MLP. 4 points/block, 64 channel-threads.
// ---------------------------------------------------------------------------
__global__ __launch_bounds__(256) void fuse_kernel(
    const float* __restrict__ f1b, const float* __restrict__ f2b,
    const float* __restrict__ cw1, const float* __restrict__ cb1,
    const float* __restrict__ cw2, const float* __restrict__ cb2,
    float* __restrict__ out)
{
    __shared__ float sfused[4][CC];
    __shared__ float shid[4][CC/2];
    __shared__ int   sidx[4][KK];

    int tid = threadIdx.x;
    int p = tid >> 6, c = tid & 63;
    int g = blockIdx.x*4 + p;

    if (c < KK) sidx[p][c] = g_idx[g*KK + c];
    __syncthreads();

    int b = g / NN;
    int rowbase = b*NN;

    float g1i = g_G1[g*CC + c];
    float g2i = g_G2[g*CC + c];
    float bb1 = f1b[c] - g1i;
    float bb2 = f2b[c] - g2i;
    float m1 = 0.f, m2 = 0.f;
    #pragma unroll 8
    for (int k = 0; k < KK; k++) {
        int j = sidx[p][k] + rowbase;
        m1 = fmaxf(m1, g_G1[j*CC + c] + bb1);
        m2 = fmaxf(m2, g_G2[j*CC + c] + bb2);
    }
    sfused[p][c] = m1 + m2;
    __syncthreads();

    if (c < CC/2) {
        float a = cb1[c];
        #pragma unroll
        for (int u = 0; u < CC; u++) a = fmaf(sfused[p][u], cw1[u*(CC/2) + c], a);
        shid[p][c] = fmaxf(a, 0.f);
    }
    __syncthreads();

    if (c < NCLS) {
        float a = cb2[c];
        #pragma unroll
        for (int u = 0; u < CC/2; u++) a = fmaf(shid[p][u], cw2[u*NCLS + c], a);
        out[g*NCLS + c] = a;
    }
}

extern "C" void kernel_launch(void* const* d_in, const int* in_sizes, int n_in,
                              void* d_out, int out_size) {
    const float* x      = (const float*)d_in[0];
    const float* enc_w1 = (const float*)d_in[1];
    const float* enc_b1 = (const float*)d_in[2];
    const float* enc_w2 = (const float*)d_in[3];
    const float* enc_b2 = (const float*)d_in[4];
    const float* f1_w   = (const float*)d_in[5];
    const float* f1_b   = (const float*)d_in[6];
    const float* f2_w   = (const float*)d_in[7];
    const float* f2_b   = (const float*)d_in[8];
    const float* cls_w1 = (const float*)d_in[9];
    const float* cls_b1 = (const float*)d_in[10];
    const float* cls_w2 = (const float*)d_in[11];
    const float* cls_b2 = (const float*)d_in[12];

    encoder_kernel<<<(BN + 255)/256, 256>>>(x, enc_w1, enc_b1, enc_w2, enc_b2,
                                            f1_w, f2_w);

    const int knn_smem = NN * (int)sizeof(float4);   // 128000 B
    cudaFuncSetAttribute(knn_kernel, cudaFuncAttributeMaxDynamicSharedMemorySize,
                         knn_smem);
    dim3 kg((NN + 255)/256, BB);
    knn_kernel<<<kg, 256, knn_smem>>>();

    fuse_kernel<<<BN/4, 256>>>(f1_b, f2_b, cls_w1, cls_b1, cls_w2, cls_b2,
                               (float*)d_out);
}